// round 1
// baseline (speedup 1.0000x reference)
#include <cuda_runtime.h>
#include <math.h>

// ---------------- problem constants ----------------
#define BB    64
#define NIN   1024
#define NHID  1024
#define NOUT  10
#define TSN   500          // time bins
#define KS    77           // SRM kernel taps (truncated alpha kernel, tau=10)
#define KR    11           // refractory kernel taps (tau=1), REF[0]==0
#define THETA 10.0f
#define TT    20           // timesteps per spmm block
#define NTG   (TSN / TT)   // 25

// ---------------- scratch (static device memory; no allocations) ----------------
__device__ float g_srm[KS];
__device__ float g_refk[KR];
__device__ float g_w1t[(size_t)NIN * NHID];          // 4 MB, W1 transposed [i][o]
__device__ float g_z1[(size_t)BB * NHID * TSN];      // 131 MB
__device__ float g_s1[(size_t)BB * NHID * TSN];      // 131 MB
__device__ float g_z2[(size_t)BB * NOUT * TSN];      // 1.28 MB
__device__ float g_u2[(size_t)BB * NOUT * TSN];      // 1.28 MB

// ---------------- kernel tap init (double, matches python math.exp -> f32) ----------------
__global__ void init_kernel() {
    int i = threadIdx.x;
    if (i < KS) {
        double t = (double)i;
        g_srm[i] = (float)(t / 10.0 * exp(1.0 - t / 10.0));
    }
    if (i < KR) {
        double t = (double)i;
        g_refk[i] = (float)(-20.0 * t * exp(1.0 - t));   // mult = -2*theta, tau_ref = 1
    }
}

// ---------------- W1 transpose: g_w1t[i][o] = W1[o][i] ----------------
__global__ void transpose_kernel(const float* __restrict__ w1) {
    __shared__ float tile[32][33];
    int i0 = blockIdx.x * 32;
    int o0 = blockIdx.y * 32;
    for (int j = threadIdx.y; j < 32; j += 8)
        tile[j][threadIdx.x] = w1[(size_t)(o0 + j) * NIN + i0 + threadIdx.x];
    __syncthreads();
    for (int j = threadIdx.y; j < 32; j += 8)
        g_w1t[(size_t)(i0 + j) * NHID + o0 + threadIdx.x] = tile[threadIdx.x][j];
}

// ---------------- layer-1 GEMM exploiting binary-sparse input ----------------
// block = (b, t-group of TT); 256 threads, each owns 4 output rows.
// z1[b,o,t0+j] = sum over active i (ascending, matching reference order) of W1[o,i].
#define ACASE(J) case J: A[J].x += w.x; A[J].y += w.y; A[J].z += w.z; A[J].w += w.w; break;

__global__ __launch_bounds__(256) void spmm1_kernel(const float* __restrict__ x) {
    __shared__ unsigned msk[NIN];
    __shared__ short    list_s[NIN];
    __shared__ unsigned mlist[NIN];
    __shared__ int      cnt_s;

    int b  = blockIdx.y;
    int t0 = blockIdx.x * TT;
    const float* xb = x + (size_t)b * NIN * TSN + t0;

    // phase 1: per-input activity bitmask over TT timesteps
    for (int i = threadIdx.x; i < NIN; i += 256) {
        const float* xr = xb + (size_t)i * TSN;
        unsigned m = 0;
#pragma unroll
        for (int j = 0; j < TT; ++j)
            if (xr[j] != 0.0f) m |= (1u << j);
        msk[i] = m;
    }
    __syncthreads();

    // phase 2: deterministic ordered compaction (warp 0)
    if (threadIdx.x < 32) {
        int lane = threadIdx.x;
        int base = 0;
        for (int c = 0; c < NIN / 32; ++c) {
            int i = c * 32 + lane;
            unsigned mv = msk[i];
            bool a = (mv != 0u);
            unsigned bal = __ballot_sync(0xffffffffu, a);
            if (a) {
                int pos = base + __popc(bal & ((1u << lane) - 1u));
                list_s[pos] = (short)i;
                mlist[pos]  = mv;
            }
            base += __popc(bal);
        }
        if (lane == 0) cnt_s = base;
    }
    __syncthreads();
    int cnt = cnt_s;

    float4 A[TT];
#pragma unroll
    for (int j = 0; j < TT; ++j) A[j] = make_float4(0.f, 0.f, 0.f, 0.f);

    int o4 = threadIdx.x * 4;
    const float* wbase = g_w1t + o4;

    int i_first = (cnt > 0) ? (int)list_s[0] : 0;
    float4 wnext = make_float4(0.f, 0.f, 0.f, 0.f);
    if (cnt > 0) wnext = *(const float4*)(wbase + (size_t)i_first * NHID);

    for (int e = 0; e < cnt; ++e) {
        float4 w = wnext;
        unsigned m = mlist[e];
        int inext = (e + 1 < cnt) ? (int)list_s[e + 1] : i_first;
        wnext = *(const float4*)(wbase + (size_t)inext * NHID);
        while (m) {
            int j = __ffs(m) - 1;
            m &= m - 1;
            switch (j) {
                ACASE(0)  ACASE(1)  ACASE(2)  ACASE(3)  ACASE(4)
                ACASE(5)  ACASE(6)  ACASE(7)  ACASE(8)  ACASE(9)
                ACASE(10) ACASE(11) ACASE(12) ACASE(13) ACASE(14)
                ACASE(15) ACASE(16) ACASE(17) ACASE(18) ACASE(19)
            }
        }
    }

    // write out z1[b, o4+c, t0..t0+TT)
    {
        float* zr = g_z1 + ((size_t)(b * NHID + o4 + 0)) * TSN + t0;
#pragma unroll
        for (int j = 0; j < TT; ++j) zr[j] = A[j].x;
    }
    {
        float* zr = g_z1 + ((size_t)(b * NHID + o4 + 1)) * TSN + t0;
#pragma unroll
        for (int j = 0; j < TT; ++j) zr[j] = A[j].y;
    }
    {
        float* zr = g_z1 + ((size_t)(b * NHID + o4 + 2)) * TSN + t0;
#pragma unroll
        for (int j = 0; j < TT; ++j) zr[j] = A[j].z;
    }
    {
        float* zr = g_z1 + ((size_t)(b * NHID + o4 + 3)) * TSN + t0;
#pragma unroll
        for (int j = 0; j < TT; ++j) zr[j] = A[j].w;
    }
}

// ---------------- fused 77-tap causal FIR + LIF scan, one thread per (b,neuron) row ----------------
#define LIF_STEP(UIN, SOUT)                                             \
    {                                                                   \
        float u_ = (UIN) + rb[0];                                       \
        float s_ = (u_ >= THETA) ? 1.0f : 0.0f;                         \
        _Pragma("unroll")                                               \
        for (int j_ = 0; j_ < 9; ++j_) rb[j_] = rb[j_ + 1] + s_ * rk[j_ + 1]; \
        rb[9] = s_ * rk[10];                                            \
        (SOUT) = s_;                                                    \
    }

__global__ __launch_bounds__(256) void conv_scan1_kernel() {
    __shared__ float srm_s[KS];
    for (int k = threadIdx.x; k < KS; k += blockDim.x) srm_s[k] = g_srm[k];
    __syncthreads();

    float rk[KR];
#pragma unroll
    for (int j = 0; j < KR; ++j) rk[j] = g_refk[j];

    int r = blockIdx.x * blockDim.x + threadIdx.x;   // 0..65535
    const float4* z  = (const float4*)(g_z1 + (size_t)r * TSN);
    float4*       sp = (float4*)(g_s1 + (size_t)r * TSN);

    float win[80];
#pragma unroll
    for (int i = 0; i < 80; ++i) win[i] = 0.0f;
    float rb[10];
#pragma unroll
    for (int j = 0; j < 10; ++j) rb[j] = 0.0f;

    for (int c = 0; c < TSN / 4; ++c) {
#pragma unroll
        for (int i = 0; i < 76; ++i) win[i] = win[i + 4];
        float4 zz = z[c];
        win[76] = zz.x; win[77] = zz.y; win[78] = zz.z; win[79] = zz.w;

        float u0 = 0.f, u1 = 0.f, u2 = 0.f, u3 = 0.f;
#pragma unroll
        for (int k = 0; k < KS; ++k) {
            float w = srm_s[k];
            u0 += w * win[76 - k];
            u1 += w * win[77 - k];
            u2 += w * win[78 - k];
            u3 += w * win[79 - k];
        }
        float4 so;
        LIF_STEP(u0, so.x);
        LIF_STEP(u1, so.y);
        LIF_STEP(u2, so.z);
        LIF_STEP(u3, so.w);
        sp[c] = so;
    }
}

// ---------------- layer-2 GEMM: z2[b,o,t] = sum_i W2[o,i] * s1[b,i,t] ----------------
// block (32,10): warp = fixed o, 32 lanes over float4 t-groups. grid (4, BB).
__global__ __launch_bounds__(320) void dense2_kernel(const float* __restrict__ w2) {
    __shared__ float ws[NOUT * NHID];
    int lt = threadIdx.y * 32 + threadIdx.x;
    for (int k = lt; k < NOUT * NHID; k += 320) ws[k] = w2[k];
    __syncthreads();

    int q = blockIdx.x * 32 + threadIdx.x;  // float4 index along t, 0..124
    if (q >= TSN / 4) return;
    int o = threadIdx.y;
    int b = blockIdx.y;

    const float4* s1b = ((const float4*)(g_s1 + (size_t)b * NHID * TSN)) + q;
    const float*  wr  = ws + o * NHID;

    float4 acc = make_float4(0.f, 0.f, 0.f, 0.f);
    for (int i = 0; i < NHID; ++i) {
        float w = wr[i];
        float4 s = s1b[(size_t)i * (TSN / 4)];
        acc.x += w * s.x; acc.y += w * s.y; acc.z += w * s.z; acc.w += w * s.w;
    }
    float4* zo = ((float4*)(g_z2 + ((size_t)(b * NOUT + o)) * TSN)) + q;
    *zo = acc;
}

// ---------------- layer-2 conv (t-parallel: 640 rows is too few for per-row serial conv) ----------------
__global__ void conv2_kernel() {
    __shared__ float srm_s[KS];
    for (int k = threadIdx.x; k < KS; k += blockDim.x) srm_s[k] = g_srm[k];
    __syncthreads();

    int idx = blockIdx.x * blockDim.x + threadIdx.x;
    int nc = TSN / 4;
    int total = BB * NOUT * nc;
    if (idx >= total) return;
    int r = idx / nc, c = idx % nc;
    const float* z = g_z2 + (size_t)r * TSN;
    int tb = c * 4;
    float u0 = 0.f, u1 = 0.f, u2 = 0.f, u3 = 0.f;
    for (int k = 0; k < KS; ++k) {
        float w = srm_s[k];
        int t = tb - k;
        if (t + 3 >= 0) {
            if (t     >= 0) u0 += w * z[t];
            if (t + 1 >= 0) u1 += w * z[t + 1];
            if (t + 2 >= 0) u2 += w * z[t + 2];
            u3 += w * z[t + 3];
        }
    }
    float* uo = g_u2 + (size_t)r * TSN + tb;
    uo[0] = u0; uo[1] = u1; uo[2] = u2; uo[3] = u3;
}

// ---------------- layer-2 LIF scan -> final output ----------------
__global__ void scan2_kernel(float* __restrict__ out) {
    float rk[KR];
#pragma unroll
    for (int j = 0; j < KR; ++j) rk[j] = g_refk[j];

    int r = blockIdx.x * blockDim.x + threadIdx.x;
    if (r >= BB * NOUT) return;
    const float* u = g_u2 + (size_t)r * TSN;
    float* o = out + (size_t)r * TSN;

    float rb[10];
#pragma unroll
    for (int j = 0; j < 10; ++j) rb[j] = 0.0f;

    for (int t = 0; t < TSN; ++t) {
        float s;
        LIF_STEP(u[t], s);
        o[t] = s;
    }
}

// ---------------- launcher ----------------
extern "C" void kernel_launch(void* const* d_in, const int* in_sizes, int n_in,
                              void* d_out, int out_size) {
    const float* x  = (const float*)d_in[0];   // spike_input [64,1024,500]
    const float* w1 = (const float*)d_in[1];   // W1 [1024,1024]
    const float* w2 = (const float*)d_in[2];   // W2 [10,1024]
    float* out = (float*)d_out;                // s2 [64,10,500]

    init_kernel<<<1, 128>>>();
    transpose_kernel<<<dim3(32, 32), dim3(32, 8)>>>(w1);
    spmm1_kernel<<<dim3(NTG, BB), 256>>>(x);
    conv_scan1_kernel<<<BB * NHID / 256, 256>>>();
    dense2_kernel<<<dim3(4, BB), dim3(32, 10)>>>(w2);
    conv2_kernel<<<(BB * NOUT * (TSN / 4) + 255) / 256, 256>>>();
    scan2_kernel<<<(BB * NOUT + 255) / 256, 256>>>(out);
}